// round 15
// baseline (speedup 1.0000x reference)
#include <cuda_runtime.h>
#include <cuda_bf16.h>
#include <cstdint>

#define NN 100000
#define EE 1600000

// ---------------- scratch ----------------
__device__ __align__(16) __nv_bfloat16 g_Ybf[NN * 128];
__device__ __align__(16) float g_R[NN * 128];
__device__ __align__(16) float g_Z[NN * 128];
__device__ __align__(16) float g_mixF[NN * 128];
__device__ __align__(16) __nv_bfloat16 g_xhi[NN * 128];
__device__ __align__(16) __nv_bfloat16 g_xlo[NN * 128];
__device__ __align__(16) __nv_bfloat16 g_hhi[NN * 128];
__device__ __align__(16) __nv_bfloat16 g_hlo[NN * 128];
__device__ __align__(16) __nv_bfloat16 g_mhi[NN * 128];
__device__ __align__(16) __nv_bfloat16 g_mlo[NN * 128];
__device__ __align__(16) __nv_bfloat16 g_Wthi[6 * 128 * 128];
__device__ __align__(16) __nv_bfloat16 g_Wtlo[6 * 128 * 128];

__device__ int g_cntA[NN];
__device__ int g_cntB[NN];
__device__ int g_rpa[NN + 1];
__device__ int g_rpb[NN + 1];
__device__ int g_curA[NN];
__device__ int g_curB[NN];
__device__ int g_cola[EE];
__device__ int g_colb[EE];

// ---------------- helpers ----------------
__device__ __forceinline__ uint32_t pack_bf2(__nv_bfloat16 a, __nv_bfloat16 b) {
    __nv_bfloat162 t = __halves2bfloat162(a, b);
    return *reinterpret_cast<uint32_t*>(&t);
}

__device__ __forceinline__ void split_store4(float4 v, __nv_bfloat16* hi,
                                             __nv_bfloat16* lo, int off) {
    __nv_bfloat16 hx = __float2bfloat16(v.x);
    __nv_bfloat16 hy = __float2bfloat16(v.y);
    __nv_bfloat16 hz = __float2bfloat16(v.z);
    __nv_bfloat16 hw = __float2bfloat16(v.w);
    uint2 hv, lv;
    hv.x = pack_bf2(hx, hy);
    hv.y = pack_bf2(hz, hw);
    lv.x = pack_bf2(__float2bfloat16(v.x - __bfloat162float(hx)),
                    __float2bfloat16(v.y - __bfloat162float(hy)));
    lv.y = pack_bf2(__float2bfloat16(v.z - __bfloat162float(hz)),
                    __float2bfloat16(v.w - __bfloat162float(hw)));
    *reinterpret_cast<uint2*>(hi + off) = hv;
    *reinterpret_cast<uint2*>(lo + off) = lv;
}

__device__ __forceinline__ void mma_bf16(float* c, const uint32_t* a,
                                         uint32_t b0, uint32_t b1) {
    asm volatile(
        "mma.sync.aligned.m16n8k16.row.col.f32.bf16.bf16.f32 "
        "{%0,%1,%2,%3}, {%4,%5,%6,%7}, {%8,%9}, {%0,%1,%2,%3};"
        : "+f"(c[0]), "+f"(c[1]), "+f"(c[2]), "+f"(c[3])
        : "r"(a[0]), "r"(a[1]), "r"(a[2]), "r"(a[3]), "r"(b0), "r"(b1));
}

// ---------------- CSR build ----------------
__global__ void k_count(const int* __restrict__ dst, int* __restrict__ cnt, int E) {
    int i = blockIdx.x * blockDim.x + threadIdx.x;
    if (i < E) atomicAdd(&cnt[dst[i]], 1);
}

__global__ void k_scan(const int* __restrict__ cnt, int* __restrict__ rowptr, int n) {
    __shared__ int part[1024];
    int tid = threadIdx.x;
    int chunk = (n + 1023) >> 10;
    int s0 = tid * chunk;
    int s1 = min(s0 + chunk, n);
    int s = 0;
    for (int i = s0; i < s1; i++) s += cnt[i];
    part[tid] = s;
    __syncthreads();
    for (int off = 1; off < 1024; off <<= 1) {
        int v = part[tid];
        int u = (tid >= off) ? part[tid - off] : 0;
        __syncthreads();
        part[tid] = v + u;
        __syncthreads();
    }
    int run = (tid == 0) ? 0 : part[tid - 1];
    for (int i = s0; i < s1; i++) { rowptr[i] = run; run += cnt[i]; }
    if (tid == 1023) rowptr[n] = part[1023];
}

__global__ void k_fill(const int* __restrict__ src, const int* __restrict__ dst,
                       int* __restrict__ cursor, int* __restrict__ col,
                       const int* __restrict__ perm, int E) {
    int i = blockIdx.x * blockDim.x + threadIdx.x;
    if (i < E) {
        int d = dst[i];
        int pos = atomicAdd(&cursor[d], 1);
        int s = src[i];
        col[pos] = perm ? perm[s] : s;
    }
}

// ---------------- weight prep: transpose + bf16 split ----------------
__global__ void k_wprep(const float* __restrict__ Wl, const float* __restrict__ Wr,
                        __nv_bfloat16* __restrict__ Wthi, __nv_bfloat16* __restrict__ Wtlo) {
    int i = blockIdx.x * blockDim.x + threadIdx.x;
    if (i >= 6 * 16384) return;
    int m = i >> 14;
    int r = (i >> 7) & 127;
    int c = i & 127;
    const float* W = (m < 3) ? (Wl + m * 16384) : (Wr + (m - 3) * 16384);
    float v = W[r * 128 + c];
    __nv_bfloat16 h = __float2bfloat16(v);
    Wthi[m * 16384 + c * 128 + r] = h;
    Wtlo[m * 16384 + c * 128 + r] = __float2bfloat16(v - __bfloat162float(h));
}

// ---------------- x prep: split + mixup init in one pass ----------------
__global__ void k_prep_x(const float4* __restrict__ x, const int* __restrict__ perm,
                         const float* __restrict__ mixr,
                         __nv_bfloat16* __restrict__ xhi, __nv_bfloat16* __restrict__ xlo,
                         __nv_bfloat16* __restrict__ mhi, __nv_bfloat16* __restrict__ mlo,
                         int n) {
    int idx = blockIdx.x * blockDim.x + threadIdx.x;
    if (idx >= n * 32) return;
    int row = idx >> 5, lane = idx & 31;
    float4 a = __ldg(&x[idx]);
    split_store4(a, xhi, xlo, idx * 4);
    int p = __ldg(&perm[row]);
    float r = __ldg(mixr);
    float q = 1.0f - r;
    float4 b = __ldg(&x[p * 32 + lane]);
    float4 v = make_float4(r * a.x + q * b.x, r * a.y + q * b.y,
                           r * a.z + q * b.z, r * a.w + q * b.w);
    split_store4(v, mhi, mlo, idx * 4);
}

// ---------------- tensor-core GEMM (bf16x3), fp32 or bf16 output ----------------
#define PITCHW 36
template <int BFOUT>
__global__ __launch_bounds__(256) void k_gemm_tc(
    const __nv_bfloat16* __restrict__ Ahi, const __nv_bfloat16* __restrict__ Alo,
    const __nv_bfloat16* __restrict__ Wthi, const __nv_bfloat16* __restrict__ Wtlo,
    float* __restrict__ out, __nv_bfloat16* __restrict__ outbf, int M) {
    extern __shared__ uint32_t sm[];
    uint32_t* sWh = sm;
    uint32_t* sWl = sm + 128 * PITCHW;
    uint32_t* sAh = sm + 2 * 128 * PITCHW;
    uint32_t* sAl = sm + 3 * 128 * PITCHW;
    int tid = threadIdx.x;
    int w = tid >> 5, lane = tid & 31;
    int g = lane >> 2, tg = lane & 3;
    int m0 = (w & 3) * 32;
    int n0 = (w >> 2) * 64;
    int row0 = blockIdx.x * 128;

    float acc[2][8][4];
#pragma unroll
    for (int mi = 0; mi < 2; mi++)
#pragma unroll
        for (int j = 0; j < 8; j++)
#pragma unroll
            for (int q = 0; q < 4; q++) acc[mi][j][q] = 0.f;

    for (int kc = 0; kc < 2; kc++) {
        int k0 = kc * 64;
        if (kc) __syncthreads();
#pragma unroll
        for (int j = 0; j < 4; j++) {
            int f = tid + j * 256;
            int r = f >> 3, q = f & 7;
            size_t goff = (size_t)r * 256 + k0 * 2 + q * 16;
            uint4 wh = *(const uint4*)((const char*)Wthi + goff);
            uint4 wl = *(const uint4*)((const char*)Wtlo + goff);
            *(uint4*)&sWh[r * PITCHW + q * 4] = wh;
            *(uint4*)&sWl[r * PITCHW + q * 4] = wl;
            int rg = row0 + r;
            uint4 ah = make_uint4(0, 0, 0, 0), al = make_uint4(0, 0, 0, 0);
            if (rg < M) {
                size_t aoff = (size_t)rg * 256 + k0 * 2 + q * 16;
                ah = *(const uint4*)((const char*)Ahi + aoff);
                al = *(const uint4*)((const char*)Alo + aoff);
            }
            *(uint4*)&sAh[r * PITCHW + q * 4] = ah;
            *(uint4*)&sAl[r * PITCHW + q * 4] = al;
        }
        __syncthreads();
#pragma unroll
        for (int kb = 0; kb < 4; kb++) {
            int pa = kb * 8 + tg;
            uint32_t ah[2][4], al_[2][4];
#pragma unroll
            for (int mi = 0; mi < 2; mi++) {
                int rb = (m0 + mi * 16 + g) * PITCHW;
                ah[mi][0] = sAh[rb + pa];
                ah[mi][1] = sAh[rb + 8 * PITCHW + pa];
                ah[mi][2] = sAh[rb + pa + 4];
                ah[mi][3] = sAh[rb + 8 * PITCHW + pa + 4];
                al_[mi][0] = sAl[rb + pa];
                al_[mi][1] = sAl[rb + 8 * PITCHW + pa];
                al_[mi][2] = sAl[rb + pa + 4];
                al_[mi][3] = sAl[rb + 8 * PITCHW + pa + 4];
            }
#pragma unroll
            for (int j = 0; j < 8; j++) {
                int nb = (n0 + j * 8 + g) * PITCHW;
                uint32_t bh0 = sWh[nb + pa], bh1 = sWh[nb + pa + 4];
                uint32_t bl0 = sWl[nb + pa], bl1 = sWl[nb + pa + 4];
#pragma unroll
                for (int mi = 0; mi < 2; mi++) {
                    mma_bf16(acc[mi][j], ah[mi], bh0, bh1);
                    mma_bf16(acc[mi][j], ah[mi], bl0, bl1);
                    mma_bf16(acc[mi][j], al_[mi], bh0, bh1);
                }
            }
        }
    }
#pragma unroll
    for (int mi = 0; mi < 2; mi++) {
        int r1 = row0 + m0 + mi * 16 + g;
        int r2 = r1 + 8;
#pragma unroll
        for (int j = 0; j < 8; j++) {
            int cidx = n0 + j * 8 + 2 * tg;
            if (BFOUT) {
                if (r1 < M)
                    *(__nv_bfloat162*)(outbf + (size_t)r1 * 128 + cidx) =
                        __floats2bfloat162_rn(acc[mi][j][0], acc[mi][j][1]);
                if (r2 < M)
                    *(__nv_bfloat162*)(outbf + (size_t)r2 * 128 + cidx) =
                        __floats2bfloat162_rn(acc[mi][j][2], acc[mi][j][3]);
            } else {
                if (r1 < M)
                    *(float2*)(out + (size_t)r1 * 128 + cidx) = make_float2(acc[mi][j][0], acc[mi][j][1]);
                if (r2 < M)
                    *(float2*)(out + (size_t)r2 * 128 + cidx) = make_float2(acc[mi][j][2], acc[mi][j][3]);
            }
        }
    }
}

// ---------------- gather helper (bf16 Y rows, uint2 per lane) — R6 version ----------------
__device__ __forceinline__ float4 gather_mean_bf(const uint2* __restrict__ Y,
                                                 const int* __restrict__ rp,
                                                 const int* __restrict__ col,
                                                 int w, int lane) {
    int s = __ldg(&rp[w]), e = __ldg(&rp[w + 1]);
    float ax = 0.f, ay = 0.f, az = 0.f, aw = 0.f;
    int i = s;
    for (; i + 3 < e; i += 4) {
        int c0 = __ldg(&col[i + 0]);
        int c1 = __ldg(&col[i + 1]);
        int c2 = __ldg(&col[i + 2]);
        int c3 = __ldg(&col[i + 3]);
        uint2 u0 = __ldg(&Y[c0 * 32 + lane]);
        uint2 u1 = __ldg(&Y[c1 * 32 + lane]);
        uint2 u2 = __ldg(&Y[c2 * 32 + lane]);
        uint2 u3 = __ldg(&Y[c3 * 32 + lane]);
        float2 a0 = __bfloat1622float2(*(__nv_bfloat162*)&u0.x);
        float2 b0 = __bfloat1622float2(*(__nv_bfloat162*)&u0.y);
        float2 a1 = __bfloat1622float2(*(__nv_bfloat162*)&u1.x);
        float2 b1 = __bfloat1622float2(*(__nv_bfloat162*)&u1.y);
        float2 a2 = __bfloat1622float2(*(__nv_bfloat162*)&u2.x);
        float2 b2 = __bfloat1622float2(*(__nv_bfloat162*)&u2.y);
        float2 a3 = __bfloat1622float2(*(__nv_bfloat162*)&u3.x);
        float2 b3 = __bfloat1622float2(*(__nv_bfloat162*)&u3.y);
        ax += (a0.x + a1.x) + (a2.x + a3.x);
        ay += (a0.y + a1.y) + (a2.y + a3.y);
        az += (b0.x + b1.x) + (b2.x + b3.x);
        aw += (b0.y + b1.y) + (b2.y + b3.y);
    }
    for (; i < e; i++) {
        int c0 = __ldg(&col[i]);
        uint2 u0 = __ldg(&Y[c0 * 32 + lane]);
        float2 a0 = __bfloat1622float2(*(__nv_bfloat162*)&u0.x);
        float2 b0 = __bfloat1622float2(*(__nv_bfloat162*)&u0.y);
        ax += a0.x; ay += a0.y; az += b0.x; aw += b0.y;
    }
    float inv = 1.0f / (float)max(e - s, 1);
    return make_float4(ax * inv, ay * inv, az * inv, aw * inv);
}

// ---------------- fused: dual gather (2 warps/node) + mixup epilogue ----------------
// Block = 256 threads = 8 warps = 4 nodes. Even warp: CSR-A gather + epilogue.
// Odd warp: CSR-B gather -> smem. Per-gather code/access pattern identical to R6.
__global__ void k_gatherepi(const uint2* __restrict__ Y,
                            const int* __restrict__ rpa, const int* __restrict__ cola,
                            const int* __restrict__ rpb, const int* __restrict__ colb,
                            const float4* __restrict__ Z, const float4* __restrict__ R,
                            const float4* __restrict__ bias, const float* __restrict__ mixr,
                            __nv_bfloat16* __restrict__ mhi, __nv_bfloat16* __restrict__ mlo,
                            float4* __restrict__ mixF,
                            __nv_bfloat16* __restrict__ hhi, __nv_bfloat16* __restrict__ hlo,
                            int n) {
    __shared__ float4 sAggB[4][32];
    int warp = threadIdx.x >> 5;
    int lane = threadIdx.x & 31;
    int slot = warp >> 1;
    int isB = warp & 1;
    int w = blockIdx.x * 4 + slot;
    bool valid = (w < n);

    float4 agg = make_float4(0.f, 0.f, 0.f, 0.f);
    if (valid) {
        agg = isB ? gather_mean_bf(Y, rpb, colb, w, lane)
                  : gather_mean_bf(Y, rpa, cola, w, lane);
        if (isB) sAggB[slot][lane] = agg;
    }
    __syncthreads();
    if (!valid || isB) return;

    float4 aA = agg;
    float4 aB = sAggB[slot][lane];
    int idx = w * 32 + lane;
    float4 z = __ldg(&Z[idx]);
    float4 b = __ldg(&bias[lane]);
    float r = __ldg(mixr);
    float q = 1.0f - r;
    float4 sA = make_float4(fmaxf(aA.x + z.x + b.x, 0.f), fmaxf(aA.y + z.y + b.y, 0.f),
                            fmaxf(aA.z + z.z + b.z, 0.f), fmaxf(aA.w + z.w + b.w, 0.f));
    float4 sB = make_float4(fmaxf(aB.x + z.x + b.x, 0.f), fmaxf(aB.y + z.y + b.y, 0.f),
                            fmaxf(aB.z + z.z + b.z, 0.f), fmaxf(aB.w + z.w + b.w, 0.f));
    float4 mix = make_float4(r * sA.x + q * sB.x, r * sA.y + q * sB.y,
                             r * sA.z + q * sB.z, r * sA.w + q * sB.w);
    if (mixF) mixF[idx] = mix;
    else split_store4(mix, mhi, mlo, idx * 4);
    if (hhi) {
        float4 rv = __ldg(&R[idx]);
        float4 h = make_float4(
            fmaxf(aA.x + rv.x + b.x, 0.f), fmaxf(aA.y + rv.y + b.y, 0.f),
            fmaxf(aA.z + rv.z + b.z, 0.f), fmaxf(aA.w + rv.w + b.w, 0.f));
        split_store4(h, hhi, hlo, idx * 4);
    }
}

// ---------------- logits + log_softmax ----------------
__global__ __launch_bounds__(256) void k_logits(
    const float* __restrict__ X, const float* __restrict__ Wo,
    const float* __restrict__ bo, float* __restrict__ out, int n) {
    __shared__ float Ws[128 * 40];
    __shared__ float bs[40];
    int tid = threadIdx.x;
    for (int i = tid; i < 128 * 40; i += 256) Ws[i] = Wo[i];
    if (tid < 40) bs[tid] = bo[tid];
    __syncthreads();

    int row = blockIdx.x * 64 + (tid >> 2);
    int row_c = min(row, n - 1);
    int cg = (tid & 3) * 10;

    float acc[10];
#pragma unroll
    for (int j = 0; j < 10; j++) acc[j] = bs[cg + j];

    const float4* xr = (const float4*)(X + (size_t)row_c * 128);
#pragma unroll 8
    for (int k4 = 0; k4 < 32; k4++) {
        float4 xv = __ldg(&xr[k4]);
        float xs[4] = { xv.x, xv.y, xv.z, xv.w };
#pragma unroll
        for (int kk = 0; kk < 4; kk++) {
            int k = k4 * 4 + kk;
#pragma unroll
            for (int j = 0; j < 10; j++)
                acc[j] = fmaf(xs[kk], Ws[k * 40 + cg + j], acc[j]);
        }
    }
    float m = acc[0];
#pragma unroll
    for (int j = 1; j < 10; j++) m = fmaxf(m, acc[j]);
    m = fmaxf(m, __shfl_xor_sync(0xffffffffu, m, 1));
    m = fmaxf(m, __shfl_xor_sync(0xffffffffu, m, 2));
    float s = 0.f;
#pragma unroll
    for (int j = 0; j < 10; j++) s += expf(acc[j] - m);
    s += __shfl_xor_sync(0xffffffffu, s, 1);
    s += __shfl_xor_sync(0xffffffffu, s, 2);
    float lse = m + logf(s);
    if (row < n) {
#pragma unroll
        for (int j = 0; j < 10; j++) out[row * 40 + cg + j] = acc[j] - lse;
    }
}

// ---------------- launch ----------------
extern "C" void kernel_launch(void* const* d_in, const int* in_sizes, int n_in,
                              void* d_out, int out_size) {
    const float* x    = (const float*)d_in[0];
    const float* Wl   = (const float*)d_in[1];
    const float* bl   = (const float*)d_in[2];
    const float* Wr   = (const float*)d_in[3];
    const float* Wo   = (const float*)d_in[4];
    const float* bo   = (const float*)d_in[5];
    const float* mixr = (const float*)d_in[6];
    const int*   adj  = (const int*)d_in[7];
    const int*   adjb = (const int*)d_in[8];
    const int*   perm = (const int*)d_in[9];

    int N = in_sizes[0] / 128;
    int E = in_sizes[7] / 2;

    float *R, *Z, *mixF;
    __nv_bfloat16 *Ybf, *xhi, *xlo, *hhi, *hlo, *mhi, *mlo, *Wthi, *Wtlo;
    int *cntA, *cntB, *rpa, *rpb, *curA, *curB, *cola, *colb;
    cudaGetSymbolAddress((void**)&Ybf, g_Ybf);
    cudaGetSymbolAddress((void**)&R, g_R);
    cudaGetSymbolAddress((void**)&Z, g_Z);
    cudaGetSymbolAddress((void**)&mixF, g_mixF);
    cudaGetSymbolAddress((void**)&xhi, g_xhi);
    cudaGetSymbolAddress((void**)&xlo, g_xlo);
    cudaGetSymbolAddress((void**)&hhi, g_hhi);
    cudaGetSymbolAddress((void**)&hlo, g_hlo);
    cudaGetSymbolAddress((void**)&mhi, g_mhi);
    cudaGetSymbolAddress((void**)&mlo, g_mlo);
    cudaGetSymbolAddress((void**)&Wthi, g_Wthi);
    cudaGetSymbolAddress((void**)&Wtlo, g_Wtlo);
    cudaGetSymbolAddress((void**)&cntA, g_cntA);
    cudaGetSymbolAddress((void**)&cntB, g_cntB);
    cudaGetSymbolAddress((void**)&rpa, g_rpa);
    cudaGetSymbolAddress((void**)&rpb, g_rpb);
    cudaGetSymbolAddress((void**)&curA, g_curA);
    cudaGetSymbolAddress((void**)&curB, g_curB);
    cudaGetSymbolAddress((void**)&cola, g_cola);
    cudaGetSymbolAddress((void**)&colb, g_colb);

    static cudaStream_t s1 = nullptr, s2 = nullptr, s3 = nullptr;
    static cudaEvent_t ev0, evPrep, evCSRa, evCSRb, evRZ0, evHM1, evRZ1, evHM2, evZ2;
    static int inited = 0;
    const int GEMM_SMEM = 4 * 128 * PITCHW * 4;
    if (!inited) {
        cudaFuncSetAttribute(k_gemm_tc<0>, cudaFuncAttributeMaxDynamicSharedMemorySize, GEMM_SMEM);
        cudaFuncSetAttribute(k_gemm_tc<1>, cudaFuncAttributeMaxDynamicSharedMemorySize, GEMM_SMEM);
        cudaStreamCreateWithFlags(&s1, cudaStreamNonBlocking);
        cudaStreamCreateWithFlags(&s2, cudaStreamNonBlocking);
        cudaStreamCreateWithFlags(&s3, cudaStreamNonBlocking);
        cudaEventCreateWithFlags(&ev0, cudaEventDisableTiming);
        cudaEventCreateWithFlags(&evPrep, cudaEventDisableTiming);
        cudaEventCreateWithFlags(&evCSRa, cudaEventDisableTiming);
        cudaEventCreateWithFlags(&evCSRb, cudaEventDisableTiming);
        cudaEventCreateWithFlags(&evRZ0, cudaEventDisableTiming);
        cudaEventCreateWithFlags(&evHM1, cudaEventDisableTiming);
        cudaEventCreateWithFlags(&evRZ1, cudaEventDisableTiming);
        cudaEventCreateWithFlags(&evHM2, cudaEventDisableTiming);
        cudaEventCreateWithFlags(&evZ2, cudaEventDisableTiming);
        inited = 1;
    }

    int eb = (E + 255) / 256;
    int aggBlocks = (N + 3) / 4;          // 2 warps/node, 4 nodes/block
    int gemmBlocks = (N + 127) / 128;
    int n32 = N * 32;
    int epiBlocks = (n32 + 255) / 256;

    const float4* bl0 = (const float4*)bl;
    const float4* bl1 = (const float4*)(bl + 128);
    const float4* bl2 = (const float4*)(bl + 256);
    __nv_bfloat16* Wl0h = Wthi + 0 * 16384; __nv_bfloat16* Wl0l = Wtlo + 0 * 16384;
    __nv_bfloat16* Wl1h = Wthi + 1 * 16384; __nv_bfloat16* Wl1l = Wtlo + 1 * 16384;
    __nv_bfloat16* Wl2h = Wthi + 2 * 16384; __nv_bfloat16* Wl2l = Wtlo + 2 * 16384;
    __nv_bfloat16* Wr0h = Wthi + 3 * 16384; __nv_bfloat16* Wr0l = Wtlo + 3 * 16384;
    __nv_bfloat16* Wr1h = Wthi + 4 * 16384; __nv_bfloat16* Wr1l = Wtlo + 4 * 16384;
    __nv_bfloat16* Wr2h = Wthi + 5 * 16384; __nv_bfloat16* Wr2l = Wtlo + 5 * 16384;

    // ---- fork: CSR builds on s1/s2 (exact R6 schedule) ----
    cudaEventRecord(ev0, 0);
    cudaStreamWaitEvent(s1, ev0, 0);
    cudaStreamWaitEvent(s2, ev0, 0);
    cudaStreamWaitEvent(s3, ev0, 0);

    cudaMemsetAsync(cntA, 0, N * sizeof(int), s1);
    k_count<<<eb, 256, 0, s1>>>(adj + E, cntA, E);
    k_scan<<<1, 1024, 0, s1>>>(cntA, rpa, N);
    cudaMemcpyAsync(curA, rpa, N * sizeof(int), cudaMemcpyDeviceToDevice, s1);
    k_fill<<<eb, 256, 0, s1>>>(adj, adj + E, curA, cola, nullptr, E);
    cudaEventRecord(evCSRa, s1);

    cudaMemsetAsync(cntB, 0, N * sizeof(int), s2);
    k_count<<<eb, 256, 0, s2>>>(adjb + E, cntB, E);
    k_scan<<<1, 1024, 0, s2>>>(cntB, rpb, N);
    cudaMemcpyAsync(curB, rpb, N * sizeof(int), cudaMemcpyDeviceToDevice, s2);
    k_fill<<<eb, 256, 0, s2>>>(adjb, adjb + E, curB, colb, perm, E);
    cudaEventRecord(evCSRb, s2);

    // ---- prep on main (R6 order) ----
    k_wprep<<<(6 * 16384 + 255) / 256, 256>>>(Wl, Wr, Wthi, Wtlo);
    k_prep_x<<<epiBlocks, 256>>>((const float4*)x, perm, mixr, xhi, xlo, mhi, mlo, N);
    cudaEventRecord(evPrep, 0);

    // ---- layer 0 (R6 schedule) ----
    cudaStreamWaitEvent(s3, evPrep, 0);
    k_gemm_tc<0><<<gemmBlocks, 256, GEMM_SMEM, s3>>>(xhi, xlo, Wr0h, Wr0l, R, nullptr, N);
    k_gemm_tc<0><<<gemmBlocks, 256, GEMM_SMEM, s3>>>(mhi, mlo, Wr0h, Wr0l, Z, nullptr, N);
    cudaEventRecord(evRZ0, s3);
    k_gemm_tc<1><<<gemmBlocks, 256, GEMM_SMEM>>>(xhi, xlo, Wl0h, Wl0l, nullptr, Ybf, N);
    cudaStreamWaitEvent(0, evCSRa, 0);
    cudaStreamWaitEvent(0, evCSRb, 0);
    cudaStreamWaitEvent(0, evRZ0, 0);
    k_gatherepi<<<aggBlocks, 256>>>((const uint2*)Ybf, rpa, cola, rpb, colb,
                                    (const float4*)Z, (const float4*)R, bl0, mixr,
                                    mhi, mlo, nullptr, hhi, hlo, N);
    cudaEventRecord(evHM1, 0);

    // ---- layer 1 ----
    cudaStreamWaitEvent(s3, evHM1, 0);
    k_gemm_tc<0><<<gemmBlocks, 256, GEMM_SMEM, s3>>>(hhi, hlo, Wr1h, Wr1l, R, nullptr, N);
    k_gemm_tc<0><<<gemmBlocks, 256, GEMM_SMEM, s3>>>(mhi, mlo, Wr1h, Wr1l, Z, nullptr, N);
    cudaEventRecord(evRZ1, s3);
    k_gemm_tc<1><<<gemmBlocks, 256, GEMM_SMEM>>>(hhi, hlo, Wl1h, Wl1l, nullptr, Ybf, N);
    cudaStreamWaitEvent(0, evRZ1, 0);
    k_gatherepi<<<aggBlocks, 256>>>((const uint2*)Ybf, rpa, cola, rpb, colb,
                                    (const float4*)Z, (const float4*)R, bl1, mixr,
                                    mhi, mlo, nullptr, hhi, hlo, N);
    cudaEventRecord(evHM2, 0);

    // ---- layer 2 (no h chain) ----
    cudaStreamWaitEvent(s3, evHM2, 0);
    k_gemm_tc<0><<<gemmBlocks, 256, GEMM_SMEM, s3>>>(mhi, mlo, Wr2h, Wr2l, Z, nullptr, N);
    cudaEventRecord(evZ2, s3);
    k_gemm_tc<1><<<gemmBlocks, 256, GEMM_SMEM>>>(hhi, hlo, Wl2h, Wl2l, nullptr, Ybf, N);
    cudaStreamWaitEvent(0, evZ2, 0);
    k_gatherepi<<<aggBlocks, 256>>>((const uint2*)Ybf, rpa, cola, rpb, colb,
                                    (const float4*)Z, nullptr, bl2, mixr,
                                    nullptr, nullptr, (float4*)mixF, nullptr, nullptr, N);

    // ---- logits ----
    k_logits<<<(N + 63) / 64, 256>>>(mixF, Wo, bo, (float*)d_out, N);
}

// round 16
// speedup vs baseline: 1.1489x; 1.1489x over previous
#include <cuda_runtime.h>
#include <cuda_bf16.h>
#include <cstdint>

#define NN 100000
#define EE 1600000

// ---------------- scratch ----------------
__device__ __align__(16) __nv_bfloat16 g_Ybf[NN * 128];
__device__ __align__(16) float g_R[NN * 128];
__device__ __align__(16) float g_Z[NN * 128];
__device__ __align__(16) float g_mixF[NN * 128];
__device__ __align__(16) __nv_bfloat16 g_xbf[NN * 128];
__device__ __align__(16) __nv_bfloat16 g_hbf[NN * 128];
__device__ __align__(16) __nv_bfloat16 g_mbf[NN * 128];
__device__ __align__(16) __nv_bfloat16 g_Wthi[6 * 128 * 128];
__device__ __align__(16) __nv_bfloat16 g_Wtlo[6 * 128 * 128];

__device__ int g_cntA[NN];
__device__ int g_cntB[NN];
__device__ int g_rpa[NN + 1];
__device__ int g_rpb[NN + 1];
__device__ int g_curA[NN];
__device__ int g_curB[NN];
__device__ int g_cola[EE];
__device__ int g_colb[EE];

// ---------------- helpers ----------------
__device__ __forceinline__ void store_bf4(float4 v, __nv_bfloat16* dst, int off) {
    __nv_bfloat162 p0 = __floats2bfloat162_rn(v.x, v.y);
    __nv_bfloat162 p1 = __floats2bfloat162_rn(v.z, v.w);
    uint2 u;
    u.x = *reinterpret_cast<uint32_t*>(&p0);
    u.y = *reinterpret_cast<uint32_t*>(&p1);
    *reinterpret_cast<uint2*>(dst + off) = u;
}

__device__ __forceinline__ void mma_bf16(float* c, const uint32_t* a,
                                         uint32_t b0, uint32_t b1) {
    asm volatile(
        "mma.sync.aligned.m16n8k16.row.col.f32.bf16.bf16.f32 "
        "{%0,%1,%2,%3}, {%4,%5,%6,%7}, {%8,%9}, {%0,%1,%2,%3};"
        : "+f"(c[0]), "+f"(c[1]), "+f"(c[2]), "+f"(c[3])
        : "r"(a[0]), "r"(a[1]), "r"(a[2]), "r"(a[3]), "r"(b0), "r"(b1));
}

// ---------------- CSR build ----------------
__global__ void k_count(const int* __restrict__ dst, int* __restrict__ cnt, int E) {
    int i = blockIdx.x * blockDim.x + threadIdx.x;
    if (i < E) atomicAdd(&cnt[dst[i]], 1);
}

__global__ void k_scan(const int* __restrict__ cnt, int* __restrict__ rowptr, int n) {
    __shared__ int part[1024];
    int tid = threadIdx.x;
    int chunk = (n + 1023) >> 10;
    int s0 = tid * chunk;
    int s1 = min(s0 + chunk, n);
    int s = 0;
    for (int i = s0; i < s1; i++) s += cnt[i];
    part[tid] = s;
    __syncthreads();
    for (int off = 1; off < 1024; off <<= 1) {
        int v = part[tid];
        int u = (tid >= off) ? part[tid - off] : 0;
        __syncthreads();
        part[tid] = v + u;
        __syncthreads();
    }
    int run = (tid == 0) ? 0 : part[tid - 1];
    for (int i = s0; i < s1; i++) { rowptr[i] = run; run += cnt[i]; }
    if (tid == 1023) rowptr[n] = part[1023];
}

__global__ void k_fill(const int* __restrict__ src, const int* __restrict__ dst,
                       int* __restrict__ cursor, int* __restrict__ col,
                       const int* __restrict__ perm, int E) {
    int i = blockIdx.x * blockDim.x + threadIdx.x;
    if (i < E) {
        int d = dst[i];
        int pos = atomicAdd(&cursor[d], 1);
        int s = src[i];
        col[pos] = perm ? perm[s] : s;
    }
}

// ---------------- weight prep: transpose + bf16 split (W keeps fp32 accuracy) ----------------
__global__ void k_wprep(const float* __restrict__ Wl, const float* __restrict__ Wr,
                        __nv_bfloat16* __restrict__ Wthi, __nv_bfloat16* __restrict__ Wtlo) {
    int i = blockIdx.x * blockDim.x + threadIdx.x;
    if (i >= 6 * 16384) return;
    int m = i >> 14;
    int r = (i >> 7) & 127;
    int c = i & 127;
    const float* W = (m < 3) ? (Wl + m * 16384) : (Wr + (m - 3) * 16384);
    float v = W[r * 128 + c];
    __nv_bfloat16 h = __float2bfloat16(v);
    Wthi[m * 16384 + c * 128 + r] = h;
    Wtlo[m * 16384 + c * 128 + r] = __float2bfloat16(v - __bfloat162float(h));
}

// ---------------- x prep: bf16 round + mixup init in one pass ----------------
__global__ void k_prep_x(const float4* __restrict__ x, const int* __restrict__ perm,
                         const float* __restrict__ mixr,
                         __nv_bfloat16* __restrict__ xbf, __nv_bfloat16* __restrict__ mbf,
                         int n) {
    int idx = blockIdx.x * blockDim.x + threadIdx.x;
    if (idx >= n * 32) return;
    int row = idx >> 5, lane = idx & 31;
    float4 a = __ldg(&x[idx]);
    store_bf4(a, xbf, idx * 4);
    int p = __ldg(&perm[row]);
    float r = __ldg(mixr);
    float q = 1.0f - r;
    float4 b = __ldg(&x[p * 32 + lane]);
    float4 v = make_float4(r * a.x + q * b.x, r * a.y + q * b.y,
                           r * a.z + q * b.z, r * a.w + q * b.w);
    store_bf4(v, mbf, idx * 4);
}

// ---------------- tensor-core GEMM (bf16x2: A bf16, W split), fp32 or bf16 output ----------------
#define PITCHW 36
template <int BFOUT>
__global__ __launch_bounds__(256) void k_gemm_tc(
    const __nv_bfloat16* __restrict__ A,
    const __nv_bfloat16* __restrict__ Wthi, const __nv_bfloat16* __restrict__ Wtlo,
    float* __restrict__ out, __nv_bfloat16* __restrict__ outbf, int M) {
    extern __shared__ uint32_t sm[];
    uint32_t* sWh = sm;
    uint32_t* sWl = sm + 128 * PITCHW;
    uint32_t* sA  = sm + 2 * 128 * PITCHW;
    int tid = threadIdx.x;
    int w = tid >> 5, lane = tid & 31;
    int g = lane >> 2, tg = lane & 3;
    int m0 = (w & 3) * 32;
    int n0 = (w >> 2) * 64;
    int row0 = blockIdx.x * 128;

    float acc[2][8][4];
#pragma unroll
    for (int mi = 0; mi < 2; mi++)
#pragma unroll
        for (int j = 0; j < 8; j++)
#pragma unroll
            for (int q = 0; q < 4; q++) acc[mi][j][q] = 0.f;

    for (int kc = 0; kc < 2; kc++) {
        int k0 = kc * 64;
        if (kc) __syncthreads();
#pragma unroll
        for (int j = 0; j < 4; j++) {
            int f = tid + j * 256;
            int r = f >> 3, q = f & 7;
            size_t goff = (size_t)r * 256 + k0 * 2 + q * 16;
            uint4 wh = *(const uint4*)((const char*)Wthi + goff);
            uint4 wl = *(const uint4*)((const char*)Wtlo + goff);
            *(uint4*)&sWh[r * PITCHW + q * 4] = wh;
            *(uint4*)&sWl[r * PITCHW + q * 4] = wl;
            int rg = row0 + r;
            uint4 av = make_uint4(0, 0, 0, 0);
            if (rg < M) {
                size_t aoff = (size_t)rg * 256 + k0 * 2 + q * 16;
                av = *(const uint4*)((const char*)A + aoff);
            }
            *(uint4*)&sA[r * PITCHW + q * 4] = av;
        }
        __syncthreads();
#pragma unroll
        for (int kb = 0; kb < 4; kb++) {
            int pa = kb * 8 + tg;
            uint32_t ah[2][4];
#pragma unroll
            for (int mi = 0; mi < 2; mi++) {
                int rb = (m0 + mi * 16 + g) * PITCHW;
                ah[mi][0] = sA[rb + pa];
                ah[mi][1] = sA[rb + 8 * PITCHW + pa];
                ah[mi][2] = sA[rb + pa + 4];
                ah[mi][3] = sA[rb + 8 * PITCHW + pa + 4];
            }
#pragma unroll
            for (int j = 0; j < 8; j++) {
                int nb = (n0 + j * 8 + g) * PITCHW;
                uint32_t bh0 = sWh[nb + pa], bh1 = sWh[nb + pa + 4];
                uint32_t bl0 = sWl[nb + pa], bl1 = sWl[nb + pa + 4];
#pragma unroll
                for (int mi = 0; mi < 2; mi++) {
                    mma_bf16(acc[mi][j], ah[mi], bh0, bh1);
                    mma_bf16(acc[mi][j], ah[mi], bl0, bl1);
                }
            }
        }
    }
#pragma unroll
    for (int mi = 0; mi < 2; mi++) {
        int r1 = row0 + m0 + mi * 16 + g;
        int r2 = r1 + 8;
#pragma unroll
        for (int j = 0; j < 8; j++) {
            int cidx = n0 + j * 8 + 2 * tg;
            if (BFOUT) {
                if (r1 < M)
                    *(__nv_bfloat162*)(outbf + (size_t)r1 * 128 + cidx) =
                        __floats2bfloat162_rn(acc[mi][j][0], acc[mi][j][1]);
                if (r2 < M)
                    *(__nv_bfloat162*)(outbf + (size_t)r2 * 128 + cidx) =
                        __floats2bfloat162_rn(acc[mi][j][2], acc[mi][j][3]);
            } else {
                if (r1 < M)
                    *(float2*)(out + (size_t)r1 * 128 + cidx) = make_float2(acc[mi][j][0], acc[mi][j][1]);
                if (r2 < M)
                    *(float2*)(out + (size_t)r2 * 128 + cidx) = make_float2(acc[mi][j][2], acc[mi][j][3]);
            }
        }
    }
}

// ---------------- gather helper (bf16 Y rows, uint2 per lane) — R6 version ----------------
__device__ __forceinline__ float4 gather_mean_bf(const uint2* __restrict__ Y,
                                                 const int* __restrict__ rp,
                                                 const int* __restrict__ col,
                                                 int w, int lane) {
    int s = __ldg(&rp[w]), e = __ldg(&rp[w + 1]);
    float ax = 0.f, ay = 0.f, az = 0.f, aw = 0.f;
    int i = s;
    for (; i + 3 < e; i += 4) {
        int c0 = __ldg(&col[i + 0]);
        int c1 = __ldg(&col[i + 1]);
        int c2 = __ldg(&col[i + 2]);
        int c3 = __ldg(&col[i + 3]);
        uint2 u0 = __ldg(&Y[c0 * 32 + lane]);
        uint2 u1 = __ldg(&Y[c1 * 32 + lane]);
        uint2 u2 = __ldg(&Y[c2 * 32 + lane]);
        uint2 u3 = __ldg(&Y[c3 * 32 + lane]);
        float2 a0 = __bfloat1622float2(*(__nv_bfloat162*)&u0.x);
        float2 b0 = __bfloat1622float2(*(__nv_bfloat162*)&u0.y);
        float2 a1 = __bfloat1622float2(*(__nv_bfloat162*)&u1.x);
        float2 b1 = __bfloat1622float2(*(__nv_bfloat162*)&u1.y);
        float2 a2 = __bfloat1622float2(*(__nv_bfloat162*)&u2.x);
        float2 b2 = __bfloat1622float2(*(__nv_bfloat162*)&u2.y);
        float2 a3 = __bfloat1622float2(*(__nv_bfloat162*)&u3.x);
        float2 b3 = __bfloat1622float2(*(__nv_bfloat162*)&u3.y);
        ax += (a0.x + a1.x) + (a2.x + a3.x);
        ay += (a0.y + a1.y) + (a2.y + a3.y);
        az += (b0.x + b1.x) + (b2.x + b3.x);
        aw += (b0.y + b1.y) + (b2.y + b3.y);
    }
    for (; i < e; i++) {
        int c0 = __ldg(&col[i]);
        uint2 u0 = __ldg(&Y[c0 * 32 + lane]);
        float2 a0 = __bfloat1622float2(*(__nv_bfloat162*)&u0.x);
        float2 b0 = __bfloat1622float2(*(__nv_bfloat162*)&u0.y);
        ax += a0.x; ay += a0.y; az += b0.x; aw += b0.y;
    }
    float inv = 1.0f / (float)max(e - s, 1);
    return make_float4(ax * inv, ay * inv, az * inv, aw * inv);
}

// ---------------- fused: dual gather + mixup epilogue (R6 structure, bf16 outputs) ----------------
__global__ void k_gatherepi(const uint2* __restrict__ Y,
                            const int* __restrict__ rpa, const int* __restrict__ cola,
                            const int* __restrict__ rpb, const int* __restrict__ colb,
                            const float4* __restrict__ Z, const float4* __restrict__ R,
                            const float4* __restrict__ bias, const float* __restrict__ mixr,
                            __nv_bfloat16* __restrict__ mbf,
                            float4* __restrict__ mixF,
                            __nv_bfloat16* __restrict__ hbf,
                            int n) {
    int w = (blockIdx.x * blockDim.x + threadIdx.x) >> 5;
    int lane = threadIdx.x & 31;
    if (w >= n) return;
    float4 aA = gather_mean_bf(Y, rpa, cola, w, lane);
    float4 aB = gather_mean_bf(Y, rpb, colb, w, lane);
    int idx = w * 32 + lane;
    float4 z = __ldg(&Z[idx]);
    float4 b = __ldg(&bias[lane]);
    float r = __ldg(mixr);
    float q = 1.0f - r;
    float4 sA = make_float4(fmaxf(aA.x + z.x + b.x, 0.f), fmaxf(aA.y + z.y + b.y, 0.f),
                            fmaxf(aA.z + z.z + b.z, 0.f), fmaxf(aA.w + z.w + b.w, 0.f));
    float4 sB = make_float4(fmaxf(aB.x + z.x + b.x, 0.f), fmaxf(aB.y + z.y + b.y, 0.f),
                            fmaxf(aB.z + z.z + b.z, 0.f), fmaxf(aB.w + z.w + b.w, 0.f));
    float4 mix = make_float4(r * sA.x + q * sB.x, r * sA.y + q * sB.y,
                             r * sA.z + q * sB.z, r * sA.w + q * sB.w);
    if (mixF) mixF[idx] = mix;
    else store_bf4(mix, mbf, idx * 4);
    if (hbf) {
        float4 rv = __ldg(&R[idx]);
        float4 h = make_float4(
            fmaxf(aA.x + rv.x + b.x, 0.f), fmaxf(aA.y + rv.y + b.y, 0.f),
            fmaxf(aA.z + rv.z + b.z, 0.f), fmaxf(aA.w + rv.w + b.w, 0.f));
        store_bf4(h, hbf, idx * 4);
    }
}

// ---------------- logits + log_softmax ----------------
__global__ __launch_bounds__(256) void k_logits(
    const float* __restrict__ X, const float* __restrict__ Wo,
    const float* __restrict__ bo, float* __restrict__ out, int n) {
    __shared__ float Ws[128 * 40];
    __shared__ float bs[40];
    int tid = threadIdx.x;
    for (int i = tid; i < 128 * 40; i += 256) Ws[i] = Wo[i];
    if (tid < 40) bs[tid] = bo[tid];
    __syncthreads();

    int row = blockIdx.x * 64 + (tid >> 2);
    int row_c = min(row, n - 1);
    int cg = (tid & 3) * 10;

    float acc[10];
#pragma unroll
    for (int j = 0; j < 10; j++) acc[j] = bs[cg + j];

    const float4* xr = (const float4*)(X + (size_t)row_c * 128);
#pragma unroll 8
    for (int k4 = 0; k4 < 32; k4++) {
        float4 xv = __ldg(&xr[k4]);
        float xs[4] = { xv.x, xv.y, xv.z, xv.w };
#pragma unroll
        for (int kk = 0; kk < 4; kk++) {
            int k = k4 * 4 + kk;
#pragma unroll
            for (int j = 0; j < 10; j++)
                acc[j] = fmaf(xs[kk], Ws[k * 40 + cg + j], acc[j]);
        }
    }
    float m = acc[0];
#pragma unroll
    for (int j = 1; j < 10; j++) m = fmaxf(m, acc[j]);
    m = fmaxf(m, __shfl_xor_sync(0xffffffffu, m, 1));
    m = fmaxf(m, __shfl_xor_sync(0xffffffffu, m, 2));
    float s = 0.f;
#pragma unroll
    for (int j = 0; j < 10; j++) s += expf(acc[j] - m);
    s += __shfl_xor_sync(0xffffffffu, s, 1);
    s += __shfl_xor_sync(0xffffffffu, s, 2);
    float lse = m + logf(s);
    if (row < n) {
#pragma unroll
        for (int j = 0; j < 10; j++) out[row * 40 + cg + j] = acc[j] - lse;
    }
}

// ---------------- launch ----------------
extern "C" void kernel_launch(void* const* d_in, const int* in_sizes, int n_in,
                              void* d_out, int out_size) {
    const float* x    = (const float*)d_in[0];
    const float* Wl   = (const float*)d_in[1];
    const float* bl   = (const float*)d_in[2];
    const float* Wr   = (const float*)d_in[3];
    const float* Wo   = (const float*)d_in[4];
    const float* bo   = (const float*)d_in[5];
    const float* mixr = (const float*)d_in[6];
    const int*   adj  = (const int*)d_in[7];
    const int*   adjb = (const int*)d_in[8];
    const int*   perm = (const int*)d_in[9];

    int N = in_sizes[0] / 128;
    int E = in_sizes[7] / 2;

    float *R, *Z, *mixF;
    __nv_bfloat16 *Ybf, *xbf, *hbf, *mbf, *Wthi, *Wtlo;
    int *cntA, *cntB, *rpa, *rpb, *curA, *curB, *cola, *colb;
    cudaGetSymbolAddress((void**)&Ybf, g_Ybf);
    cudaGetSymbolAddress((void**)&R, g_R);
    cudaGetSymbolAddress((void**)&Z, g_Z);
    cudaGetSymbolAddress((void**)&mixF, g_mixF);
    cudaGetSymbolAddress((void**)&xbf, g_xbf);
    cudaGetSymbolAddress((void**)&hbf, g_hbf);
    cudaGetSymbolAddress((void**)&mbf, g_mbf);
    cudaGetSymbolAddress((void**)&Wthi, g_Wthi);
    cudaGetSymbolAddress((void**)&Wtlo, g_Wtlo);
    cudaGetSymbolAddress((void**)&cntA, g_cntA);
    cudaGetSymbolAddress((void**)&cntB, g_cntB);
    cudaGetSymbolAddress((void**)&rpa, g_rpa);
    cudaGetSymbolAddress((void**)&rpb, g_rpb);
    cudaGetSymbolAddress((void**)&curA, g_curA);
    cudaGetSymbolAddress((void**)&curB, g_curB);
    cudaGetSymbolAddress((void**)&cola, g_cola);
    cudaGetSymbolAddress((void**)&colb, g_colb);

    static cudaStream_t s1 = nullptr, s2 = nullptr, s3 = nullptr;
    static cudaEvent_t ev0, evPrep, evCSRa, evCSRb, evRZ0, evHM1, evRZ1, evHM2, evZ2;
    static int inited = 0;
    const int GEMM_SMEM = 3 * 128 * PITCHW * 4;   // 55296 B
    if (!inited) {
        cudaFuncSetAttribute(k_gemm_tc<0>, cudaFuncAttributeMaxDynamicSharedMemorySize, GEMM_SMEM);
        cudaFuncSetAttribute(k_gemm_tc<1>, cudaFuncAttributeMaxDynamicSharedMemorySize, GEMM_SMEM);
        cudaStreamCreateWithFlags(&s1, cudaStreamNonBlocking);
        cudaStreamCreateWithFlags(&s2, cudaStreamNonBlocking);
        cudaStreamCreateWithFlags(&s3, cudaStreamNonBlocking);
        cudaEventCreateWithFlags(&ev0, cudaEventDisableTiming);
        cudaEventCreateWithFlags(&evPrep, cudaEventDisableTiming);
        cudaEventCreateWithFlags(&evCSRa, cudaEventDisableTiming);
        cudaEventCreateWithFlags(&evCSRb, cudaEventDisableTiming);
        cudaEventCreateWithFlags(&evRZ0, cudaEventDisableTiming);
        cudaEventCreateWithFlags(&evHM1, cudaEventDisableTiming);
        cudaEventCreateWithFlags(&evRZ1, cudaEventDisableTiming);
        cudaEventCreateWithFlags(&evHM2, cudaEventDisableTiming);
        cudaEventCreateWithFlags(&evZ2, cudaEventDisableTiming);
        inited = 1;
    }

    int eb = (E + 255) / 256;
    int aggBlocks = (N + 7) / 8;
    int gemmBlocks = (N + 127) / 128;
    int n32 = N * 32;
    int epiBlocks = (n32 + 255) / 256;

    const float4* bl0 = (const float4*)bl;
    const float4* bl1 = (const float4*)(bl + 128);
    const float4* bl2 = (const float4*)(bl + 256);
    __nv_bfloat16* Wl0h = Wthi + 0 * 16384; __nv_bfloat16* Wl0l = Wtlo + 0 * 16384;
    __nv_bfloat16* Wl1h = Wthi + 1 * 16384; __nv_bfloat16* Wl1l = Wtlo + 1 * 16384;
    __nv_bfloat16* Wl2h = Wthi + 2 * 16384; __nv_bfloat16* Wl2l = Wtlo + 2 * 16384;
    __nv_bfloat16* Wr0h = Wthi + 3 * 16384; __nv_bfloat16* Wr0l = Wtlo + 3 * 16384;
    __nv_bfloat16* Wr1h = Wthi + 4 * 16384; __nv_bfloat16* Wr1l = Wtlo + 4 * 16384;
    __nv_bfloat16* Wr2h = Wthi + 5 * 16384; __nv_bfloat16* Wr2l = Wtlo + 5 * 16384;

    // ---- fork: CSR builds on s1/s2 (exact R6 schedule) ----
    cudaEventRecord(ev0, 0);
    cudaStreamWaitEvent(s1, ev0, 0);
    cudaStreamWaitEvent(s2, ev0, 0);
    cudaStreamWaitEvent(s3, ev0, 0);

    cudaMemsetAsync(cntA, 0, N * sizeof(int), s1);
    k_count<<<eb, 256, 0, s1>>>(adj + E, cntA, E);
    k_scan<<<1, 1024, 0, s1>>>(cntA, rpa, N);
    cudaMemcpyAsync(curA, rpa, N * sizeof(int), cudaMemcpyDeviceToDevice, s1);
    k_fill<<<eb, 256, 0, s1>>>(adj, adj + E, curA, cola, nullptr, E);
    cudaEventRecord(evCSRa, s1);

    cudaMemsetAsync(cntB, 0, N * sizeof(int), s2);
    k_count<<<eb, 256, 0, s2>>>(adjb + E, cntB, E);
    k_scan<<<1, 1024, 0, s2>>>(cntB, rpb, N);
    cudaMemcpyAsync(curB, rpb, N * sizeof(int), cudaMemcpyDeviceToDevice, s2);
    k_fill<<<eb, 256, 0, s2>>>(adjb, adjb + E, curB, colb, perm, E);
    cudaEventRecord(evCSRb, s2);

    // ---- prep on main (R6 order) ----
    k_wprep<<<(6 * 16384 + 255) / 256, 256>>>(Wl, Wr, Wthi, Wtlo);
    k_prep_x<<<epiBlocks, 256>>>((const float4*)x, perm, mixr, xbf, mbf, N);
    cudaEventRecord(evPrep, 0);

    // ---- layer 0: Y on main, R+Z serial on s3 (R6 schedule) ----
    cudaStreamWaitEvent(s3, evPrep, 0);
    k_gemm_tc<0><<<gemmBlocks, 256, GEMM_SMEM, s3>>>(xbf, Wr0h, Wr0l, R, nullptr, N);
    k_gemm_tc<0><<<gemmBlocks, 256, GEMM_SMEM, s3>>>(mbf, Wr0h, Wr0l, Z, nullptr, N);
    cudaEventRecord(evRZ0, s3);
    k_gemm_tc<1><<<gemmBlocks, 256, GEMM_SMEM>>>(xbf, Wl0h, Wl0l, nullptr, Ybf, N);
    cudaStreamWaitEvent(0, evCSRa, 0);
    cudaStreamWaitEvent(0, evCSRb, 0);
    cudaStreamWaitEvent(0, evRZ0, 0);
    k_gatherepi<<<aggBlocks, 256>>>((const uint2*)Ybf, rpa, cola, rpb, colb,
                                    (const float4*)Z, (const float4*)R, bl0, mixr,
                                    mbf, nullptr, hbf, N);
    cudaEventRecord(evHM1, 0);

    // ---- layer 1 ----
    cudaStreamWaitEvent(s3, evHM1, 0);
    k_gemm_tc<0><<<gemmBlocks, 256, GEMM_SMEM, s3>>>(hbf, Wr1h, Wr1l, R, nullptr, N);
    k_gemm_tc<0><<<gemmBlocks, 256, GEMM_SMEM, s3>>>(mbf, Wr1h, Wr1l, Z, nullptr, N);
    cudaEventRecord(evRZ1, s3);
    k_gemm_tc<1><<<gemmBlocks, 256, GEMM_SMEM>>>(hbf, Wl1h, Wl1l, nullptr, Ybf, N);
    cudaStreamWaitEvent(0, evRZ1, 0);
    k_gatherepi<<<aggBlocks, 256>>>((const uint2*)Ybf, rpa, cola, rpb, colb,
                                    (const float4*)Z, (const float4*)R, bl1, mixr,
                                    mbf, nullptr, hbf, N);
    cudaEventRecord(evHM2, 0);

    // ---- layer 2 (no h chain) ----
    cudaStreamWaitEvent(s3, evHM2, 0);
    k_gemm_tc<0><<<gemmBlocks, 256, GEMM_SMEM, s3>>>(mbf, Wr2h, Wr2l, Z, nullptr, N);
    cudaEventRecord(evZ2, s3);
    k_gemm_tc<1><<<gemmBlocks, 256, GEMM_SMEM>>>(hbf, Wl2h, Wl2l, nullptr, Ybf, N);
    cudaStreamWaitEvent(0, evZ2, 0);
    k_gatherepi<<<aggBlocks, 256>>>((const uint2*)Ybf, rpa, cola, rpb, colb,
                                    (const float4*)Z, nullptr, bl2, mixr,
                                    nullptr, (float4*)mixF, nullptr, N);

    // ---- logits ----
    k_logits<<<(N + 63) / 64, 256>>>(mixF, Wo, bo, (float*)d_out, N);
}